// round 2
// baseline (speedup 1.0000x reference)
#include <cuda_runtime.h>
#include <cstdint>

#define N_PTS     4096
#define N_QUERY   (64 * 552)     // 35328
#define NSAMPLE   32
#define FEAT_D    32
#define FEAT_H    64
#define K_KEYPTS  64
#define RADIUS2   4.0f
#define OUT_GROUP_OFF (K_KEYPTS * 6)
#define FULL 0xffffffffu

// ---------------- device scratch (no allocs allowed) ----------------
__device__ float  g_feat[N_PTS * FEAT_D];   // tgt features, point-major [n][f]
__device__ float4 g_xyz4[N_PTS];            // tgt xyz + ||p||^2
__device__ float  g_z[N_PTS];               // src pre-softplus scores

// ---------------- Kernel A: MLP for src (scores) and tgt (features) ----------------
__global__ void mlp_kernel(const float* __restrict__ src, const float* __restrict__ tgt,
                           const float* __restrict__ W1, const float* __restrict__ b1,
                           const float* __restrict__ W2, const float* __restrict__ b2,
                           const float* __restrict__ Wq, const float* __restrict__ bq)
{
    __shared__ float sW1[FEAT_H * 6], sb1[FEAT_H];
    __shared__ float sW2[FEAT_D * FEAT_H], sb2[FEAT_D], sWq[FEAT_D];
    int tid = threadIdx.x;
    for (int i = tid; i < FEAT_H * 6; i += blockDim.x) sW1[i] = W1[i];
    for (int i = tid; i < FEAT_H; i += blockDim.x)     sb1[i] = b1[i];
    for (int i = tid; i < FEAT_D * FEAT_H; i += blockDim.x) sW2[i] = W2[i];
    for (int i = tid; i < FEAT_D; i += blockDim.x)     sb2[i] = b2[i];
    for (int i = tid; i < FEAT_D; i += blockDim.x)     sWq[i] = Wq[i];
    __syncthreads();

    int n = blockIdx.x * blockDim.x + tid;
    if (n >= N_PTS) return;
    bool is_tgt = (blockIdx.y == 1);
    const float* pts = is_tgt ? tgt : src;

    float p[6];
#pragma unroll
    for (int c = 0; c < 6; c++) p[c] = pts[c * N_PTS + n];

    float facc[FEAT_D];
#pragma unroll
    for (int f = 0; f < FEAT_D; f++) facc[f] = 0.0f;

    for (int o = 0; o < FEAT_H; o++) {
        float a = 0.0f;
#pragma unroll
        for (int c = 0; c < 6; c++) a = fmaf(sW1[o * 6 + c], p[c], a);
        a += sb1[o];
        float h = fmaxf(a, 0.0f);
#pragma unroll
        for (int f = 0; f < FEAT_D; f++) facc[f] = fmaf(sW2[f * FEAT_H + o], h, facc[f]);
    }

    if (is_tgt) {
#pragma unroll
        for (int f = 0; f < FEAT_D; f++) {
            float v = fmaxf(facc[f] + sb2[f], 0.0f);
            g_feat[n * FEAT_D + f] = v;
        }
        float px2 = __fmul_rn(p[0], p[0]);
        float py2 = __fmul_rn(p[1], p[1]);
        float pz2 = __fmul_rn(p[2], p[2]);
        float pp = __fadd_rn(__fadd_rn(px2, py2), pz2);
        g_xyz4[n] = make_float4(p[0], p[1], p[2], pp);
    } else {
        float z = 0.0f;
#pragma unroll
        for (int f = 0; f < FEAT_D; f++) {
            float v = fmaxf(facc[f] + sb2[f], 0.0f);
            z = fmaf(sWq[f], v, z);
        }
        z += bq[0];
        g_z[n] = z;   // softplus is monotonic -> rank on pre-activation
    }
}

// ---------------- Kernel B: top-64 scores -> src_keypts ----------------
__global__ void topk_kernel(const float* __restrict__ src_pts, float* __restrict__ out)
{
    __shared__ unsigned long long skey[N_PTS];
    __shared__ unsigned long long warpmax[16];
    __shared__ int sel[K_KEYPTS];
    int tid = threadIdx.x;

    for (int i = tid; i < N_PTS; i += 512) {
        float z = g_z[i];
        unsigned u = __float_as_uint(z);
        u = (u & 0x80000000u) ? ~u : (u | 0x80000000u);  // monotone total order
        // low 32 bits: larger = smaller index, so max-key picks lower index on ties
        skey[i] = ((unsigned long long)u << 32) | (unsigned long long)(0xFFFFFFFFu - (unsigned)i);
    }
    __syncthreads();

    for (int k = 0; k < K_KEYPTS; k++) {
        unsigned long long best = 0ull;
        for (int i = tid; i < N_PTS; i += 512) {
            unsigned long long v = skey[i];
            best = (v > best) ? v : best;
        }
#pragma unroll
        for (int off = 16; off; off >>= 1) {
            unsigned long long o = __shfl_xor_sync(FULL, best, off);
            best = (o > best) ? o : best;
        }
        if ((tid & 31) == 0) warpmax[tid >> 5] = best;
        __syncthreads();
        if (tid == 0) {
            unsigned long long b = warpmax[0];
            for (int w = 1; w < 16; w++) b = (warpmax[w] > b) ? warpmax[w] : b;
            int idx = (int)(0xFFFFFFFFu - (unsigned)(b & 0xFFFFFFFFull));
            sel[k] = idx;
            skey[idx] = 0ull;
        }
        __syncthreads();
    }

    if (tid < K_KEYPTS * 6) {
        int k = tid / 6, c = tid % 6;
        out[k * 6 + c] = src_pts[c * N_PTS + sel[k]];
    }
}

// ---------------- Kernel C: ball-query nearest-32 + gather ----------------
// One warp per query. Points (xyz,pp) cached in SMEM, lane-sorted streaming top-32.
__global__ void __launch_bounds__(512)
group_kernel(const float* __restrict__ cand, float* __restrict__ out)
{
    extern __shared__ float4 sp[];   // 4096 * 16B = 64KB
    for (int i = threadIdx.x; i < N_PTS; i += 512) sp[i] = g_xyz4[i];
    __syncthreads();

    int warp = threadIdx.x >> 5;
    int lane = threadIdx.x & 31;
    int m = blockIdx.x * 16 + warp;          // 2208 * 16 == 35328 exactly

    float qx = cand[m * 3 + 0];
    float qy = cand[m * 3 + 1];
    float qz = cand[m * 3 + 2];
    float qq = __fadd_rn(__fadd_rn(__fmul_rn(qx, qx), __fmul_rn(qy, qy)), __fmul_rn(qz, qz));

    const float INF = __int_as_float(0x7f800000);
    // lane-sorted list: lane l holds l-th smallest (dist, idx); ascending, ties by index
    float bd = INF;
    int   bi = 0;
    float thr = INF;   // == bd at lane 31, replicated in every lane

    for (int base = 0; base < N_PTS; base += 32) {
        float4 P = sp[base + lane];
        float dot = fmaf(qz, P.z, fmaf(qy, P.y, __fmul_rn(qx, P.x)));
        float sq  = __fadd_rn(__fsub_rn(qq, __fmul_rn(2.0f, dot)), P.w);
        bool ok = (sq <= RADIUS2) && (sq < thr);
        unsigned mask = __ballot_sync(FULL, ok);
        while (mask) {
            int s = __ffs(mask) - 1;
            mask &= mask - 1;
            float dc = __shfl_sync(FULL, sq, s);
            if (dc < thr) {                       // warp-uniform (dc, thr uniform)
                int ic = base + s;
                float pd = __shfl_up_sync(FULL, bd, 1);
                int   pi = __shfl_up_sync(FULL, bi, 1);
                if (bd > dc) {                    // shift-insert; lane 31 falls off
                    bool take = (lane == 0) || (pd <= dc);
                    bd = take ? dc : pd;
                    bi = take ? ic : pi;
                }
                thr = __shfl_sync(FULL, bd, 31);
            }
        }
    }

    // padding: invalid slots take slot-0's index (0 if no valid neighbor at all)
    int nv  = __popc(__ballot_sync(FULL, bd <= RADIUS2));
    int bi0 = __shfl_sync(FULL, bi, 0);
    int fidx = (lane < nv) ? bi : ((nv > 0) ? bi0 : 0);

    // coalesced write of 32*35 = 1120 floats per query
    float* op = out + OUT_GROUP_OFF + (size_t)m * (NSAMPLE * 35);
    int slot = 0, t = lane;                      // element e = it*32 + lane; slot=e/35, t=e%35
#pragma unroll 1
    for (int it = 0; it < 35; it++) {
        int is = __shfl_sync(FULL, fidx, slot);
        float val;
        if (t < 3) {
            float4 P = sp[is];
            float pc = (t == 0) ? P.x : ((t == 1) ? P.y : P.z);
            float qc = (t == 0) ? qx  : ((t == 1) ? qy  : qz);
            val = __fsub_rn(pc, qc);             // tgt_xyz[idx] - q
        } else {
            val = g_feat[is * FEAT_D + (t - 3)];
        }
        op[it * 32 + lane] = val;
        t += 32;
        if (t >= 35) { t -= 35; slot++; }
    }
}

// ---------------- launch ----------------
extern "C" void kernel_launch(void* const* d_in, const int* in_sizes, int n_in,
                              void* d_out, int out_size)
{
    const float* src  = (const float*)d_in[0];
    const float* tgt  = (const float*)d_in[1];
    const float* cand = (const float*)d_in[2];
    const float* W1   = (const float*)d_in[3];
    const float* b1   = (const float*)d_in[4];
    const float* W2   = (const float*)d_in[5];
    const float* b2   = (const float*)d_in[6];
    const float* Wq   = (const float*)d_in[7];
    const float* bq   = (const float*)d_in[8];
    float* out = (float*)d_out;

    // one-time opt-in for 64KB dynamic smem; keep the captured region launches-only
    static bool s_attr_done = false;
    if (!s_attr_done) {
        cudaFuncSetAttribute(group_kernel, cudaFuncAttributeMaxDynamicSharedMemorySize, 65536);
        s_attr_done = true;
    }

    mlp_kernel<<<dim3(16, 2), 256>>>(src, tgt, W1, b1, W2, b2, Wq, bq);
    topk_kernel<<<1, 512>>>(src, out);
    group_kernel<<<N_QUERY / 16, 512, 65536>>>(cand, out);
}